// round 17
// baseline (speedup 1.0000x reference)
#include <cuda_runtime.h>
#include <cuda_fp16.h>
#include <cstdint>

#define TT 512
#define SDIM 8
#define ODIM 4
#define NTHREADS 256
#define NCTA 128

#define KP3 200   // padded row stride (halves) for 192-k weight blocks
#define KP2 136   // padded row stride for 128-k blocks
#define SSTR 264  // fp16 state row stride (halves): [W@0B | I@128B | A@256B | RI@384B]
#define GP  68    // fp32 temp row stride (floats)

struct __align__(16) Smem {
    __half win[64 * KP3];   // [j][ W|I|A ]   (W_from_*)
    __half wz [64 * KP3];   // [j][ Wn|I|A ]  (I_z)
    __half wr [64 * KP3];   // [j][ Wn|I|A ]  (I_r)
    __half wh [64 * KP3];   // [j][ Wn|rI|A ] (I_h)
    __half wa [64 * KP3];   // [j][ Wn|In|A ] (A_from_*)
    __half wg [64 * KP2];   // [j][ I|A ]     (W_gate)
    __half wag[64 * KP2];   // [j][ Wn|In ]   (A_gate)
    __half st [8 * SSTR];   // fp16 states per row
    float gtmp[8 * GP];     // Wg sigm
    float ztmp[8 * GP];     // z
    float pWI[8 * GP];      // W_in [W|I]-part + tanh(enc)   (ho -> hc)
    float pR [8 * GP];      // r [I|A]-part                  (ho -> hc)
    float pH [8 * GP];      // h A-part                      (ho -> hc)
    float sWe[8 * 64];      // encoder weights
    float sphi[64 * ODIM];  // phi
    float sphib[ODIM];
    float xs[8][SDIM];
};

extern __shared__ char smem_raw[];

__device__ __forceinline__ float tanh_f(float x) {
    float y;
    asm("tanh.approx.f32 %0, %1;" : "=f"(y) : "f"(x));
    return y;
}
__device__ __forceinline__ float sigm_f(float x) {
    float y;
    asm("tanh.approx.f32 %0, %1;" : "=f"(y) : "f"(0.5f * x));
    return fmaf(0.5f, y, 0.5f);
}
__device__ __forceinline__ uint32_t s2u(const void* p) {
    uint32_t a;
    asm("{ .reg .u64 t; cvta.to.shared.u64 t, %1; cvt.u32.u64 %0, t; }"
        : "=r"(a) : "l"(p));
    return a;
}
__device__ __forceinline__ void ldsm4(uint32_t addr, uint32_t& r0, uint32_t& r1,
                                      uint32_t& r2, uint32_t& r3) {
    asm volatile("ldmatrix.sync.aligned.m8n8.x4.shared.b16 {%0,%1,%2,%3}, [%4];"
                 : "=r"(r0), "=r"(r1), "=r"(r2), "=r"(r3) : "r"(addr));
}
__device__ __forceinline__ uint32_t lds32(uint32_t addr) {
    uint32_t v;
    asm volatile("ld.shared.b32 %0, [%1];" : "=r"(v) : "r"(addr));
    return v;
}
__device__ __forceinline__ void mma16816(float& d0, float& d1, float& d2, float& d3,
                                         uint32_t a0, uint32_t a1, uint32_t a2,
                                         uint32_t a3, uint32_t b0, uint32_t b1) {
    asm volatile(
        "mma.sync.aligned.m16n8k16.row.col.f32.f16.f16.f32 "
        "{%0,%1,%2,%3}, {%4,%5,%6,%7}, {%8,%9}, {%0,%1,%2,%3};"
        : "+f"(d0), "+f"(d1), "+f"(d2), "+f"(d3)
        : "r"(a0), "r"(a1), "r"(a2), "r"(a3), "r"(b0), "r"(b1));
}

#define BSYNC(id, n)   asm volatile("bar.sync %0, %1;"   :: "r"(id), "r"(n) : "memory")
#define BARRIVE(id, n) asm volatile("bar.arrive %0, %1;" :: "r"(id), "r"(n) : "memory")

template <int N>
__device__ __forceinline__ void mma_acc(const uint32_t (*f)[4], uint32_t bb,
                                        int bstart, float (&d)[4], float (&e)[4]) {
    uint32_t b0[N], b1[N];
#pragma unroll
    for (int i = 0; i < N; i++) {
        b0[i] = lds32(bb + bstart + i * 32);
        b1[i] = lds32(bb + bstart + i * 32 + 16);
    }
#pragma unroll
    for (int i = 0; i < N; i++) {
        float* a = (i & 1) ? e : d;
        mma16816(a[0], a[1], a[2], a[3],
                 f[i][0], f[i][1], f[i][2], f[i][3], b0[i], b1[i]);
    }
}

__device__ __forceinline__ void stage_mat(__half* dst, int Kp, int koff,
                                          const float* __restrict__ src, int K) {
#pragma unroll 1
    for (int i = threadIdx.x; i < K * 64; i += NTHREADS) {
        int k = i >> 6, j = i & 63;
        dst[j * Kp + koff + k] = __float2half(src[i]);
    }
}

// Barriers:
//  b1 (256): ho arrive (gWg stored; pWI stored in prior shadow) -> hc sync at W-epi
//  b3 (256): hc arrive (W stored)                               -> ho sync (z_W, WWI_W)
//  b4 (256): ho arrive (z stored)                               -> hc sync at I-epi
//  b5 (256): ho arrive (pR/pH stored + P5 st[A] reads done)     -> hc sync at r-step
//  b6 (256): hc arrive (I stored)                               -> ho sync (shadow)
//  b9 (256): hc arrive (A stored; pre-arrived once)             -> ho sync at step top
//  b2 (128): hc internal ordering (4x per step)
//  b7 (128): ho internal (xs staged before shadow enc)

__global__ void __launch_bounds__(NTHREADS, 1)
anima_kernel(const float* __restrict__ x,
             const float* __restrict__ we_w, const float* __restrict__ we_b,
             const float* __restrict__ WfW, const float* __restrict__ WfI,
             const float* __restrict__ WfA,
             const float* __restrict__ Wg_w, const float* __restrict__ Wg_b,
             const float* __restrict__ Iz_w, const float* __restrict__ Iz_b,
             const float* __restrict__ Ir_w, const float* __restrict__ Ir_b,
             const float* __restrict__ Ih_w, const float* __restrict__ Ih_b,
             const float* __restrict__ AfW, const float* __restrict__ AfI,
             const float* __restrict__ AfA,
             const float* __restrict__ Ag_w, const float* __restrict__ Ag_b,
             const float* __restrict__ phi_w, const float* __restrict__ phi_b,
             float* __restrict__ out) {
    Smem* S = reinterpret_cast<Smem*>(smem_raw);
    const int tid = threadIdx.x;

    stage_mat(S->win, KP3, 0, WfW, 64);
    stage_mat(S->win, KP3, 64, WfI, 64);
    stage_mat(S->win, KP3, 128, WfA, 64);
    stage_mat(S->wz, KP3, 0, Iz_w, 192);
    stage_mat(S->wr, KP3, 0, Ir_w, 192);
    stage_mat(S->wh, KP3, 0, Ih_w, 192);
    stage_mat(S->wa, KP3, 0, AfW, 64);
    stage_mat(S->wa, KP3, 64, AfI, 64);
    stage_mat(S->wa, KP3, 128, AfA, 64);
    stage_mat(S->wg, KP2, 0, Wg_w, 128);
    stage_mat(S->wag, KP2, 0, Ag_w, 128);

#pragma unroll 1
    for (int i = tid; i < 8 * SSTR / 2; i += NTHREADS)
        reinterpret_cast<uint32_t*>(S->st)[i] = 0u;
#pragma unroll 1
    for (int i = tid; i < 8 * GP; i += NTHREADS) {
        S->gtmp[i] = 0.f; S->ztmp[i] = 0.f;
        S->pWI[i] = 0.f; S->pR[i] = 0.f; S->pH[i] = 0.f;
    }
#pragma unroll 1
    for (int i = tid; i < 8 * 64; i += NTHREADS) S->sWe[i] = we_w[i];
#pragma unroll 1
    for (int i = tid; i < 64 * ODIM; i += NTHREADS) S->sphi[i] = phi_w[i];
    if (tid < ODIM) S->sphib[tid] = phi_b[tid];

    const int lane = tid & 31, w = tid >> 5;
    const int jt = w & 3;
    const int g = lane >> 2, t4 = lane & 3;
    const int rl = (lane & 7) | (((lane >> 3) & 1) << 3);
    const int c8 = (lane >> 4) * 8;
    const int j1 = jt * 16 + g, j2 = j1 + 8;
    const int n0 = 2 * t4, n1 = n0 + 1;
    const long base = (long)blockIdx.x * 8;
    const uint32_t arow3 = ((jt * 16 + rl) * KP3 + c8) * 2;
    const uint32_t arow2 = ((jt * 16 + rl) * KP2 + c8) * 2;
    const uint32_t bb = s2u(S->st) + g * (SSTR * 2) + t4 * 4;

    // x(0) staged by ho threads (ltid<64)
    const int ltid = tid & 127;
    const int xrow = ltid >> 3, xc = ltid & 7;
    const float* xptr = x + (base + xrow) * (TT * SDIM) + xc;
    if (tid >= 128 && ltid < 64) S->xs[xrow][xc] = xptr[0];
    __syncthreads();

    if (w < 4) {
        // ================= hc: the serial chain =================
        uint32_t fWA[4][4], fRW[4][4], fHW[4][4], fHRI[4][4];
        uint32_t fAgW[4][4], fAgI[4][4], fAW[4][4], fAI[4][4], fAA[4][4];
        {
            const uint32_t aWin = s2u(S->win) + arow3;
            const uint32_t aWr = s2u(S->wr) + arow3;
            const uint32_t aWh = s2u(S->wh) + arow3;
            const uint32_t aWa = s2u(S->wa) + arow3;
            const uint32_t aWag = s2u(S->wag) + arow2;
#pragma unroll
            for (int k = 0; k < 4; k++) {
                ldsm4(aWin + (8 + k) * 32, fWA[k][0], fWA[k][1], fWA[k][2], fWA[k][3]);
                ldsm4(aWr + k * 32, fRW[k][0], fRW[k][1], fRW[k][2], fRW[k][3]);
                ldsm4(aWh + k * 32, fHW[k][0], fHW[k][1], fHW[k][2], fHW[k][3]);
                ldsm4(aWh + (4 + k) * 32, fHRI[k][0], fHRI[k][1], fHRI[k][2], fHRI[k][3]);
                ldsm4(aWag + k * 32, fAgW[k][0], fAgW[k][1], fAgW[k][2], fAgW[k][3]);
                ldsm4(aWag + (4 + k) * 32, fAgI[k][0], fAgI[k][1], fAgI[k][2], fAgI[k][3]);
                ldsm4(aWa + k * 32, fAW[k][0], fAW[k][1], fAW[k][2], fAW[k][3]);
                ldsm4(aWa + (4 + k) * 32, fAI[k][0], fAI[k][1], fAI[k][2], fAI[k][3]);
                ldsm4(aWa + (8 + k) * 32, fAA[k][0], fAA[k][1], fAA[k][2], fAA[k][3]);
            }
        }
        const float br1 = Ir_b[j1], br2 = Ir_b[j2];
        const float bh1 = Ih_b[j1], bh2 = Ih_b[j2];
        const float ba1 = Ag_b[j1], ba2 = Ag_b[j2];
        float Ifp[4] = {0.f, 0.f, 0.f, 0.f};

        BARRIVE(9, 256);   // pre-arrival for ho's t=0 top

        for (int t_ = 0; t_ < TT; t_++) {
            // top: A(t-1)-dependent parts
            float aW[4] = {}, aWe[4] = {};
            mma_acc<4>(fWA, bb, 256, aW, aWe);
            float aA[4] = {}, aAe[4] = {};
            mma_acc<4>(fAA, bb, 256, aA, aAe);

            BSYNC(1, 256);     // gWg + pWI ready
            {
                float w00 = tanh_f(aW[0] + aWe[0] + S->pWI[n0 * GP + j1]) * S->gtmp[n0 * GP + j1];
                float w10 = tanh_f(aW[1] + aWe[1] + S->pWI[n1 * GP + j1]) * S->gtmp[n1 * GP + j1];
                float w01 = tanh_f(aW[2] + aWe[2] + S->pWI[n0 * GP + j2]) * S->gtmp[n0 * GP + j2];
                float w11 = tanh_f(aW[3] + aWe[3] + S->pWI[n1 * GP + j2]) * S->gtmp[n1 * GP + j2];
                S->st[n0 * SSTR + j1] = __float2half(w00);
                S->st[n1 * SSTR + j1] = __float2half(w10);
                S->st[n0 * SSTR + j2] = __float2half(w01);
                S->st[n1 * SSTR + j2] = __float2half(w11);
            }
            BSYNC(2, 128);
            BARRIVE(3, 256);   // -> ho: W ready
            BSYNC(5, 256);     // pR, pH ready (also orders ho st[A] reads before our A store)

            // r + overlapped W-part mmas for h/Ag/A
            float rr[4] = {}, rre[4] = {};
            mma_acc<4>(fRW, bb, 0, rr, rre);
            float hh[4] = {}, hhe[4] = {};
            mma_acc<4>(fHW, bb, 0, hh, hhe);
            float ag[4] = {}, age[4] = {};
            mma_acc<4>(fAgW, bb, 0, ag, age);
            mma_acc<4>(fAW, bb, 0, aA, aAe);
            {
                float r00 = sigm_f(br1 + rr[0] + rre[0] + S->pR[n0 * GP + j1]);
                float r10 = sigm_f(br1 + rr[1] + rre[1] + S->pR[n1 * GP + j1]);
                float r01 = sigm_f(br2 + rr[2] + rre[2] + S->pR[n0 * GP + j2]);
                float r11 = sigm_f(br2 + rr[3] + rre[3] + S->pR[n1 * GP + j2]);
                S->st[n0 * SSTR + 192 + j1] = __float2half(r00 * Ifp[0]);
                S->st[n1 * SSTR + 192 + j1] = __float2half(r10 * Ifp[1]);
                S->st[n0 * SSTR + 192 + j2] = __float2half(r01 * Ifp[2]);
                S->st[n1 * SSTR + 192 + j2] = __float2half(r11 * Ifp[3]);
            }
            BSYNC(2, 128);     // RI visible

            mma_acc<4>(fHRI, bb, 384, hh, hhe);
            BSYNC(4, 256);     // z ready
            {
                float h00 = tanh_f(hh[0] + hhe[0] + S->pH[n0 * GP + j1] + bh1);
                float h10 = tanh_f(hh[1] + hhe[1] + S->pH[n1 * GP + j1] + bh1);
                float h01 = tanh_f(hh[2] + hhe[2] + S->pH[n0 * GP + j2] + bh2);
                float h11 = tanh_f(hh[3] + hhe[3] + S->pH[n1 * GP + j2] + bh2);
                float z00 = S->ztmp[n0 * GP + j1], z10 = S->ztmp[n1 * GP + j1];
                float z01 = S->ztmp[n0 * GP + j2], z11 = S->ztmp[n1 * GP + j2];
                Ifp[0] += z00 * (h00 - Ifp[0]);
                Ifp[1] += z10 * (h10 - Ifp[1]);
                Ifp[2] += z01 * (h01 - Ifp[2]);
                Ifp[3] += z11 * (h11 - Ifp[3]);
                S->st[n0 * SSTR + 64 + j1] = __float2half(Ifp[0]);
                S->st[n1 * SSTR + 64 + j1] = __float2half(Ifp[1]);
                S->st[n0 * SSTR + 64 + j2] = __float2half(Ifp[2]);
                S->st[n1 * SSTR + 64 + j2] = __float2half(Ifp[3]);
            }
            BSYNC(2, 128);
            BARRIVE(6, 256);   // -> ho: I ready

            mma_acc<4>(fAgI, bb, 128, ag, age);
            mma_acc<4>(fAI, bb, 128, aA, aAe);
            {
                float g00 = sigm_f(ba1 + ag[0] + age[0]);
                float g10 = sigm_f(ba1 + ag[1] + age[1]);
                float g01 = sigm_f(ba2 + ag[2] + age[2]);
                float g11 = sigm_f(ba2 + ag[3] + age[3]);
                S->st[n0 * SSTR + 128 + j1] = __float2half(tanh_f(aA[0] + aAe[0]) * g00);
                S->st[n1 * SSTR + 128 + j1] = __float2half(tanh_f(aA[1] + aAe[1]) * g10);
                S->st[n0 * SSTR + 128 + j2] = __float2half(tanh_f(aA[2] + aAe[2]) * g01);
                S->st[n1 * SSTR + 128 + j2] = __float2half(tanh_f(aA[3] + aAe[3]) * g11);
            }
            BSYNC(2, 128);
            BARRIVE(9, 256);   // -> ho: A ready
        }
    } else {
        // ================= ho: gates, partials, P5, x =================
        uint32_t fWgI[4][4], fWgA[4][4], fZW[4][4], fZI[4][4], fZA[4][4];
        uint32_t fRI_[4][4], fRA[4][4], fHA[4][4], fWW[4][4], fWI[4][4];
        {
            const uint32_t aWg = s2u(S->wg) + arow2;
            const uint32_t aWz = s2u(S->wz) + arow3;
            const uint32_t aWr = s2u(S->wr) + arow3;
            const uint32_t aWh = s2u(S->wh) + arow3;
            const uint32_t aWin = s2u(S->win) + arow3;
#pragma unroll
            for (int k = 0; k < 4; k++) {
                ldsm4(aWg + k * 32, fWgI[k][0], fWgI[k][1], fWgI[k][2], fWgI[k][3]);
                ldsm4(aWg + (4 + k) * 32, fWgA[k][0], fWgA[k][1], fWgA[k][2], fWgA[k][3]);
                ldsm4(aWz + k * 32, fZW[k][0], fZW[k][1], fZW[k][2], fZW[k][3]);
                ldsm4(aWz + (4 + k) * 32, fZI[k][0], fZI[k][1], fZI[k][2], fZI[k][3]);
                ldsm4(aWz + (8 + k) * 32, fZA[k][0], fZA[k][1], fZA[k][2], fZA[k][3]);
                ldsm4(aWr + (4 + k) * 32, fRI_[k][0], fRI_[k][1], fRI_[k][2], fRI_[k][3]);
                ldsm4(aWr + (8 + k) * 32, fRA[k][0], fRA[k][1], fRA[k][2], fRA[k][3]);
                ldsm4(aWh + (8 + k) * 32, fHA[k][0], fHA[k][1], fHA[k][2], fHA[k][3]);
                ldsm4(aWin + k * 32, fWW[k][0], fWW[k][1], fWW[k][2], fWW[k][3]);
                ldsm4(aWin + (4 + k) * 32, fWI[k][0], fWI[k][1], fWI[k][2], fWI[k][3]);
            }
        }
        const float bg1 = Wg_b[j1], bg2 = Wg_b[j2];
        const float bz1 = Iz_b[j1], bz2 = Iz_b[j2];
        const float be1 = we_b[j1], be2 = we_b[j2];
        // P5 mapping
        const int o5 = lane & 3, sg = (lane >> 2) & 3, rsel = lane >> 4;
        const int prow = (w - 4) * 2 + rsel;

        float xv = (ltid < 64) ? xptr[SDIM] : 0.f;

        // pre-loop: pWI(0) = tanh(enc(0))
        {
            float e00 = be1, e10 = be1, e01 = be2, e11 = be2;
#pragma unroll
            for (int s = 0; s < 8; s++) {
                float w1v = S->sWe[s * 64 + j1], w2v = S->sWe[s * 64 + j2];
                e00 = fmaf(S->xs[n0][s], w1v, e00);
                e10 = fmaf(S->xs[n1][s], w1v, e10);
                e01 = fmaf(S->xs[n0][s], w2v, e01);
                e11 = fmaf(S->xs[n1][s], w2v, e11);
            }
            S->pWI[n0 * GP + j1] = tanh_f(e00);
            S->pWI[n1 * GP + j1] = tanh_f(e10);
            S->pWI[n0 * GP + j2] = tanh_f(e01);
            S->pWI[n1 * GP + j2] = tanh_f(e11);
        }

        float cG[4] = {}, cGe[4] = {}, cZ[4] = {}, cZe[4] = {};
        float cR[4] = {}, cRe[4] = {};

        for (int t_ = 0; t_ < TT; t_++) {
            BSYNC(9, 256);     // A(t-1) ready
            // Wg A-part -> gate -> signal hc ASAP
            mma_acc<4>(fWgA, bb, 256, cG, cGe);
            S->gtmp[n0 * GP + j1] = sigm_f(bg1 + cG[0] + cGe[0]);
            S->gtmp[n1 * GP + j1] = sigm_f(bg1 + cG[1] + cGe[1]);
            S->gtmp[n0 * GP + j2] = sigm_f(bg2 + cG[2] + cGe[2]);
            S->gtmp[n1 * GP + j2] = sigm_f(bg2 + cG[3] + cGe[3]);
            BARRIVE(1, 256);
#pragma unroll
            for (int i = 0; i < 4; i++) { cG[i] = 0.f; cGe[i] = 0.f; }

            // remaining A-parts
            mma_acc<4>(fRA, bb, 256, cR, cRe);
            float hA[4] = {}, hAe[4] = {};
            mma_acc<4>(fHA, bb, 256, hA, hAe);
            mma_acc<4>(fZA, bb, 256, cZ, cZe);
            S->pR[n0 * GP + j1] = cR[0] + cRe[0];
            S->pR[n1 * GP + j1] = cR[1] + cRe[1];
            S->pR[n0 * GP + j2] = cR[2] + cRe[2];
            S->pR[n1 * GP + j2] = cR[3] + cRe[3];
            S->pH[n0 * GP + j1] = hA[0] + hAe[0];
            S->pH[n1 * GP + j1] = hA[1] + hAe[1];
            S->pH[n0 * GP + j2] = hA[2] + hAe[2];
            S->pH[n1 * GP + j2] = hA[3] + hAe[3];
#pragma unroll
            for (int i = 0; i < 4; i++) { cR[i] = 0.f; cRe[i] = 0.f; }

            // P5: action(t-1) from st[A](t-1) — must precede b5 arrive
            if (t_ > 0) {
                const __half* ap = S->st + prow * SSTR + 128 + sg * 16;
                uint4 v0 = *reinterpret_cast<const uint4*>(ap);
                uint4 v1 = *reinterpret_cast<const uint4*>(ap + 8);
                const __half2* h0 = reinterpret_cast<const __half2*>(&v0);
                const __half2* h1 = reinterpret_cast<const __half2*>(&v1);
                float p = 0.f;
#pragma unroll
                for (int q = 0; q < 4; q++) {
                    float2 f0 = __half22float2(h0[q]);
                    float2 f1 = __half22float2(h1[q]);
                    p = fmaf(f0.x, S->sphi[(sg * 16 + 2 * q) * 4 + o5], p);
                    p = fmaf(f0.y, S->sphi[(sg * 16 + 2 * q + 1) * 4 + o5], p);
                    p = fmaf(f1.x, S->sphi[(sg * 16 + 8 + 2 * q) * 4 + o5], p);
                    p = fmaf(f1.y, S->sphi[(sg * 16 + 9 + 2 * q) * 4 + o5], p);
                }
                p += __shfl_xor_sync(0xffffffffu, p, 4);
                p += __shfl_xor_sync(0xffffffffu, p, 8);
                if (sg == 0)
                    out[(base + prow) * (TT * ODIM) + (t_ - 1) * ODIM + o5] =
                        p + S->sphib[o5];
            }
            BARRIVE(5, 256);   // pR/pH stored, st[A] reads done

            if (ltid < 64) {
                S->xs[xrow][xc] = xv;  // x(t+1)
                if (t_ + 2 < TT) xv = xptr[(t_ + 2) * SDIM];
            }

            BSYNC(3, 256);     // W ready
            mma_acc<4>(fZW, bb, 0, cZ, cZe);
            S->ztmp[n0 * GP + j1] = sigm_f(bz1 + cZ[0] + cZe[0]);
            S->ztmp[n1 * GP + j1] = sigm_f(bz1 + cZ[1] + cZe[1]);
            S->ztmp[n0 * GP + j2] = sigm_f(bz2 + cZ[2] + cZe[2]);
            S->ztmp[n1 * GP + j2] = sigm_f(bz2 + cZ[3] + cZe[3]);
            BARRIVE(4, 256);
#pragma unroll
            for (int i = 0; i < 4; i++) { cZ[i] = 0.f; cZe[i] = 0.f; }

            float dWI[4] = {}, dWIe[4] = {};
            mma_acc<4>(fWW, bb, 0, dWI, dWIe);   // W_in W-part (uses W(t))

            BSYNC(6, 256);     // I ready
            BSYNC(7, 128);     // xs(t+1) visible within ho
            // shadow: I(t)-dependent parts for step t+1
            mma_acc<4>(fWgI, bb, 128, cG, cGe);
            mma_acc<4>(fZI, bb, 128, cZ, cZe);
            mma_acc<4>(fRI_, bb, 128, cR, cRe);
            mma_acc<4>(fWI, bb, 128, dWI, dWIe);
            {
                float e00 = be1, e10 = be1, e01 = be2, e11 = be2;
#pragma unroll
                for (int s = 0; s < 8; s++) {
                    float w1v = S->sWe[s * 64 + j1], w2v = S->sWe[s * 64 + j2];
                    e00 = fmaf(S->xs[n0][s], w1v, e00);
                    e10 = fmaf(S->xs[n1][s], w1v, e10);
                    e01 = fmaf(S->xs[n0][s], w2v, e01);
                    e11 = fmaf(S->xs[n1][s], w2v, e11);
                }
                S->pWI[n0 * GP + j1] = dWI[0] + dWIe[0] + tanh_f(e00);
                S->pWI[n1 * GP + j1] = dWI[1] + dWIe[1] + tanh_f(e10);
                S->pWI[n0 * GP + j2] = dWI[2] + dWIe[2] + tanh_f(e01);
                S->pWI[n1 * GP + j2] = dWI[3] + dWIe[3] + tanh_f(e11);
            }
        }
        // final action(TT-1)
        BSYNC(9, 256);
        {
            const __half* ap = S->st + prow * SSTR + 128 + sg * 16;
            uint4 v0 = *reinterpret_cast<const uint4*>(ap);
            uint4 v1 = *reinterpret_cast<const uint4*>(ap + 8);
            const __half2* h0 = reinterpret_cast<const __half2*>(&v0);
            const __half2* h1 = reinterpret_cast<const __half2*>(&v1);
            float p = 0.f;
#pragma unroll
            for (int q = 0; q < 4; q++) {
                float2 f0 = __half22float2(h0[q]);
                float2 f1 = __half22float2(h1[q]);
                p = fmaf(f0.x, S->sphi[(sg * 16 + 2 * q) * 4 + o5], p);
                p = fmaf(f0.y, S->sphi[(sg * 16 + 2 * q + 1) * 4 + o5], p);
                p = fmaf(f1.x, S->sphi[(sg * 16 + 8 + 2 * q) * 4 + o5], p);
                p = fmaf(f1.y, S->sphi[(sg * 16 + 9 + 2 * q) * 4 + o5], p);
            }
            p += __shfl_xor_sync(0xffffffffu, p, 4);
            p += __shfl_xor_sync(0xffffffffu, p, 8);
            if (sg == 0)
                out[(base + prow) * (TT * ODIM) + (TT - 1) * ODIM + o5] =
                    p + S->sphib[o5];
        }
    }
}

extern "C" void kernel_launch(void* const* d_in, const int* in_sizes, int n_in,
                              void* d_out, int out_size) {
    (void)in_sizes; (void)n_in; (void)out_size;
    const size_t shmem = sizeof(Smem);
    cudaFuncSetAttribute(anima_kernel,
                         cudaFuncAttributeMaxDynamicSharedMemorySize,
                         (int)shmem);
    anima_kernel<<<NCTA, NTHREADS, shmem>>>(
        (const float*)d_in[0],
        (const float*)d_in[1], (const float*)d_in[2],
        (const float*)d_in[3], (const float*)d_in[4], (const float*)d_in[5],
        (const float*)d_in[6], (const float*)d_in[7],
        (const float*)d_in[8], (const float*)d_in[9],
        (const float*)d_in[10], (const float*)d_in[11],
        (const float*)d_in[12], (const float*)d_in[13],
        (const float*)d_in[14], (const float*)d_in[15], (const float*)d_in[16],
        (const float*)d_in[17], (const float*)d_in[18],
        (const float*)d_in[19], (const float*)d_in[20],
        (float*)d_out);
}